// round 3
// baseline (speedup 1.0000x reference)
#include <cuda_runtime.h>
#include <math.h>

// Pe_i_CrossAttention: fused point-transformer local attention.
// B=4, C=64, N=16384, K=16, H=8, D=8.
// Key algebraic fusion: never materialize k/v (B,H,N,K,D).
//   energy[h,k] = (Wk_h^T q_h) . nb_k          (r-vector, 67-dim per head)
//   out[h]      = Wv_h @ (sum_k attn[h,k] nb_k) (s-vector, 67-dim per head)
// -> 30k MACs/point instead of 143k.

#define B_      4
#define C_      64
#define N_      16384
#define K_      16
#define H_      8
#define CP3     67          // C + 3
#define PTS     32          // points per block
#define THREADS 256
#define NB_STRIDE 1080      // 67*16 + 8  (pad: 1080 % 32 == 24 -> 4 warp-points on disjoint bank quads)
#define PC_STRIDE 68
#define W_ELEMS (CP3 * C_)  // 4288

// smem floats: 3*4288 (W) + 32*68 (pc) + 32*1080 (nb) = 49600 -> 198400 bytes
#define SMEM_BYTES ((3 * W_ELEMS + PTS * PC_STRIDE + PTS * NB_STRIDE) * 4)

__global__ __launch_bounds__(THREADS, 1)
void pt_attn_kernel(const float* __restrict__ pcd,
                    const float* __restrict__ neighbors,
                    const float* __restrict__ xyz,
                    const float* __restrict__ Wq,
                    const float* __restrict__ Wk,
                    const float* __restrict__ Wv,
                    const int*   __restrict__ idx_all,
                    float*       __restrict__ out)
{
    extern __shared__ float sm[];
    float* WqT = sm;                       // [67][64] permuted
    float* WkT = WqT + W_ELEMS;
    float* WvT = WkT + W_ELEMS;
    float* pc  = WvT + W_ELEMS;            // [32][68]
    float* nb  = pc + PTS * PC_STRIDE;     // [32][1080]

    const int tid = threadIdx.x;
    const int g0  = blockIdx.x * PTS;      // global point base (block never crosses batch: 32 | 16384)
    const int b   = g0 / N_;
    const int n0  = g0 % N_;

    // ---- W transposed + permuted: WT[c*64 + d4*32 + h*4 + dd] = W[(h*8+d4*4+dd)*67 + c]
    // Reader: 8 heads' float4 loads cover 128 contiguous bytes -> conflict-free.
    for (int e = tid; e < W_ELEMS; e += THREADS) {
        int c  = e >> 6;
        int j  = e & 63;
        int d4 = j >> 5, h = (j >> 2) & 7, dd = j & 3;
        int o  = h * 8 + d4 * 4 + dd;
        WqT[e] = Wq[o * CP3 + c];
        WkT[e] = Wk[o * CP3 + c];
        WvT[e] = Wv[o * CP3 + c];
    }
    // ---- center features: pc[p][0..63] = pcd, pc[p][64..66] = xyz (coalesced over p)
    for (int e = tid; e < C_ * PTS; e += THREADS) {
        int c = e >> 5, p = e & 31;
        pc[p * PC_STRIDE + c] = pcd[(b * C_ + c) * N_ + n0 + p];
    }
    for (int e = tid; e < 3 * PTS; e += THREADS) {
        int j = e >> 5, p = e & 31;
        pc[p * PC_STRIDE + 64 + j] = xyz[(b * 3 + j) * N_ + n0 + p];
    }
    // ---- neighbor features as float4 (fully coalesced: 512 consecutive floats per c-row)
    {
        const float4* nbr4 = (const float4*)neighbors;
        for (int f = tid; f < C_ * PTS * 4; f += THREADS) {
            int c   = f >> 7;
            int rem = f & 127;
            int p   = rem >> 2;
            int k4  = rem & 3;
            float4 v = nbr4[((size_t)(b * C_ + c) * N_ + n0 + p) * 4 + k4];
            *(float4*)(nb + p * NB_STRIDE + c * K_ + k4 * 4) = v;
        }
    }
    // ---- gathered xyz rows (xyz is 768 KB -> L2-resident)
    for (int e = tid; e < PTS * K_; e += THREADS) {
        int p = e >> 4, k = e & 15;
        int idx = idx_all[(b * N_ + n0 + p) * K_ + k];
        #pragma unroll
        for (int j = 0; j < 3; j++)
            nb[p * NB_STRIDE + (C_ + j) * K_ + k] = xyz[(b * 3 + j) * N_ + idx];
    }
    __syncthreads();

    // ---- per-thread: one (point, head)
    const int lane = tid & 31;
    const int w    = tid >> 5;
    const int psub = lane & 3;
    const int h    = lane >> 2;
    const int p    = w * 4 + psub;
    const float* nbp = nb + p * NB_STRIDE;
    const float* pcp = pc + p * PC_STRIDE;
    const int hc = h * 4;

    // q_h = Wq_h @ pcd_cat (then fold 1/sqrt(D))
    float q[8];
    #pragma unroll
    for (int d = 0; d < 8; d++) q[d] = 0.f;
    #pragma unroll
    for (int c = 0; c < CP3; c++) {
        float x = pcp[c];
        float4 w0 = *(const float4*)(WqT + c * 64 + hc);
        float4 w1 = *(const float4*)(WqT + c * 64 + 32 + hc);
        q[0] = fmaf(w0.x, x, q[0]); q[1] = fmaf(w0.y, x, q[1]);
        q[2] = fmaf(w0.z, x, q[2]); q[3] = fmaf(w0.w, x, q[3]);
        q[4] = fmaf(w1.x, x, q[4]); q[5] = fmaf(w1.y, x, q[5]);
        q[6] = fmaf(w1.z, x, q[6]); q[7] = fmaf(w1.w, x, q[7]);
    }
    const float scl = 0.35355339059327373f;  // 1/sqrt(8)
    #pragma unroll
    for (int d = 0; d < 8; d++) q[d] *= scl;

    // r[c] = (Wk_h^T q_h)[c]
    float vec[CP3];
    #pragma unroll
    for (int c = 0; c < CP3; c++) {
        float4 w0 = *(const float4*)(WkT + c * 64 + hc);
        float4 w1 = *(const float4*)(WkT + c * 64 + 32 + hc);
        float a = fmaf(w0.x, q[0], w0.y * q[1]);
        a = fmaf(w0.z, q[2], a); a = fmaf(w0.w, q[3], a);
        a = fmaf(w1.x, q[4], a); a = fmaf(w1.y, q[5], a);
        a = fmaf(w1.z, q[6], a); a = fmaf(w1.w, q[7], a);
        vec[c] = a;
    }

    // energy[k] = r . nb_k   (16 independent accumulators)
    float e0[16];
    #pragma unroll
    for (int k = 0; k < 16; k++) e0[k] = 0.f;
    #pragma unroll
    for (int c = 0; c < CP3; c++) {
        float rc = vec[c];
        float4 nv[4];
        nv[0] = *(const float4*)(nbp + c * K_);
        nv[1] = *(const float4*)(nbp + c * K_ + 4);
        nv[2] = *(const float4*)(nbp + c * K_ + 8);
        nv[3] = *(const float4*)(nbp + c * K_ + 12);
        const float* nf = reinterpret_cast<const float*>(nv);
        #pragma unroll
        for (int k = 0; k < 16; k++) e0[k] = fmaf(rc, nf[k], e0[k]);
    }

    // softmax over 16 neighbors (thread-local)
    float m = e0[0];
    #pragma unroll
    for (int k = 1; k < 16; k++) m = fmaxf(m, e0[k]);
    float ssum = 0.f;
    #pragma unroll
    for (int k = 0; k < 16; k++) { e0[k] = __expf(e0[k] - m); ssum += e0[k]; }
    float inv = 1.f / ssum;
    #pragma unroll
    for (int k = 0; k < 16; k++) e0[k] *= inv;

    // s[c] = sum_k attn[k] * nb[c,k]  (reuse vec[])
    #pragma unroll
    for (int c = 0; c < CP3; c++) {
        float4 nv[4];
        nv[0] = *(const float4*)(nbp + c * K_);
        nv[1] = *(const float4*)(nbp + c * K_ + 4);
        nv[2] = *(const float4*)(nbp + c * K_ + 8);
        nv[3] = *(const float4*)(nbp + c * K_ + 12);
        const float* nf = reinterpret_cast<const float*>(nv);
        float s0 = 0.f, s1 = 0.f;
        #pragma unroll
        for (int k = 0; k < 8; k++) {
            s0 = fmaf(e0[k], nf[k], s0);
            s1 = fmaf(e0[k + 8], nf[k + 8], s1);
        }
        vec[c] = s0 + s1;
    }

    // out[d] = Wv_h[d] . s
    float o[8];
    #pragma unroll
    for (int d = 0; d < 8; d++) o[d] = 0.f;
    #pragma unroll
    for (int c = 0; c < CP3; c++) {
        float x = vec[c];
        float4 w0 = *(const float4*)(WvT + c * 64 + hc);
        float4 w1 = *(const float4*)(WvT + c * 64 + 32 + hc);
        o[0] = fmaf(w0.x, x, o[0]); o[1] = fmaf(w0.y, x, o[1]);
        o[2] = fmaf(w0.z, x, o[2]); o[3] = fmaf(w0.w, x, o[3]);
        o[4] = fmaf(w1.x, x, o[4]); o[5] = fmaf(w1.y, x, o[5]);
        o[6] = fmaf(w1.z, x, o[6]); o[7] = fmaf(w1.w, x, o[7]);
    }

    // out[b, h*8+d, n0+p]
    const int n = n0 + p;
    #pragma unroll
    for (int d = 0; d < 8; d++)
        out[(b * C_ + h * 8 + d) * N_ + n] = o[d];
}

extern "C" void kernel_launch(void* const* d_in, const int* in_sizes, int n_in,
                              void* d_out, int out_size)
{
    (void)in_sizes; (void)n_in; (void)out_size;
    const float* pcd       = (const float*)d_in[0];
    const float* neighbors = (const float*)d_in[1];
    const float* xyz       = (const float*)d_in[2];
    const float* Wq        = (const float*)d_in[3];
    const float* Wk        = (const float*)d_in[4];
    const float* Wv        = (const float*)d_in[5];
    const int*   idx_all   = (const int*)d_in[6];
    float* out = (float*)d_out;

    cudaFuncSetAttribute(pt_attn_kernel,
                         cudaFuncAttributeMaxDynamicSharedMemorySize, SMEM_BYTES);

    const int total_points = B_ * N_;
    const int grid = total_points / PTS;   // 2048
    pt_attn_kernel<<<grid, THREADS, SMEM_BYTES>>>(
        pcd, neighbors, xyz, Wq, Wk, Wv, idx_all, out);
}

// round 5
// speedup vs baseline: 1.7284x; 1.7284x over previous
#include <cuda_runtime.h>
#include <math.h>

// Pe_i_CrossAttention: fused point-transformer local attention.
// B=4, C=64, N=16384, K=16, H=8, D=8.
// Algebraic fusion (never materialize k/v):
//   energy[h,k] = (Wk_h^T q_h) . nb_k   with r_c computed on the fly
//   out[h]      = Wv_h @ (sum_k attn[h,k] nb_k) with s_c computed on the fly
// R3 change: streaming passes -> no 67-float per-thread arrays -> no spills.

#define B_      4
#define C_      64
#define N_      16384
#define K_      16
#define H_      8
#define CP3     67          // C + 3
#define PTS     32          // points per block
#define THREADS 256
#define NB_STRIDE 1080      // 67*16 + 8 pad
#define PC_STRIDE 68
#define W_ELEMS (CP3 * C_)  // 4288

// smem floats: 3*4288 (W) + 32*68 (pc) + 32*1080 (nb) = 49600 -> 198400 bytes
#define SMEM_BYTES ((3 * W_ELEMS + PTS * PC_STRIDE + PTS * NB_STRIDE) * 4)

__global__ __launch_bounds__(THREADS, 1)
void pt_attn_kernel(const float* __restrict__ pcd,
                    const float* __restrict__ neighbors,
                    const float* __restrict__ xyz,
                    const float* __restrict__ Wq,
                    const float* __restrict__ Wk,
                    const float* __restrict__ Wv,
                    const int*   __restrict__ idx_all,
                    float*       __restrict__ out)
{
    extern __shared__ float sm[];
    float* WqT = sm;                       // [67][64] permuted
    float* WkT = WqT + W_ELEMS;
    float* WvT = WkT + W_ELEMS;
    float* pc  = WvT + W_ELEMS;            // [32][68]
    float* nb  = pc + PTS * PC_STRIDE;     // [32][1080]

    const int tid = threadIdx.x;
    const int g0  = blockIdx.x * PTS;      // 32 | 16384 -> block never crosses batch
    const int b   = g0 / N_;
    const int n0  = g0 % N_;

    // ---- W transposed + permuted: WT[c*64 + d4*32 + h*4 + dd] = W[(h*8+d4*4+dd)*67 + c]
    // Reader: 8 heads' float4 loads cover 128 contiguous bytes -> conflict-free.
    for (int e = tid; e < W_ELEMS; e += THREADS) {
        int c  = e >> 6;
        int j  = e & 63;
        int d4 = j >> 5, h = (j >> 2) & 7, dd = j & 3;
        int o  = h * 8 + d4 * 4 + dd;
        WqT[e] = Wq[o * CP3 + c];
        WkT[e] = Wk[o * CP3 + c];
        WvT[e] = Wv[o * CP3 + c];
    }
    // ---- center features (coalesced over p)
    for (int e = tid; e < C_ * PTS; e += THREADS) {
        int c = e >> 5, p = e & 31;
        pc[p * PC_STRIDE + c] = pcd[(b * C_ + c) * N_ + n0 + p];
    }
    for (int e = tid; e < 3 * PTS; e += THREADS) {
        int j = e >> 5, p = e & 31;
        pc[p * PC_STRIDE + 64 + j] = xyz[(b * 3 + j) * N_ + n0 + p];
    }
    // ---- neighbor features as float4 (fully coalesced)
    {
        const float4* nbr4 = (const float4*)neighbors;
        for (int f = tid; f < C_ * PTS * 4; f += THREADS) {
            int c   = f >> 7;
            int rem = f & 127;
            int p   = rem >> 2;
            int k4  = rem & 3;
            float4 v = nbr4[((size_t)(b * C_ + c) * N_ + n0 + p) * 4 + k4];
            *(float4*)(nb + p * NB_STRIDE + c * K_ + k4 * 4) = v;
        }
    }
    // ---- gathered xyz rows (xyz is 768 KB -> L2-resident)
    for (int e = tid; e < PTS * K_; e += THREADS) {
        int p = e >> 4, k = e & 15;
        int idx = idx_all[(b * N_ + n0 + p) * K_ + k];
        #pragma unroll
        for (int j = 0; j < 3; j++)
            nb[p * NB_STRIDE + (C_ + j) * K_ + k] = xyz[(b * 3 + j) * N_ + idx];
    }
    __syncthreads();

    // ---- per-thread: one (point, head)
    const int lane = tid & 31;
    const int w    = tid >> 5;
    const int psub = lane & 3;
    const int h    = lane >> 2;
    const int p    = w * 4 + psub;
    const float* nbp = nb + p * NB_STRIDE;
    const float* pcp = pc + p * PC_STRIDE;
    const int hc = h * 4;

    // ======== pass 1: q_h = (1/sqrt(D)) * Wq_h @ pcd_cat ========
    float q[8];
    #pragma unroll
    for (int d = 0; d < 8; d++) q[d] = 0.f;
    #pragma unroll 2
    for (int c = 0; c < CP3; c++) {
        float x = pcp[c];
        float4 w0 = *(const float4*)(WqT + c * 64 + hc);
        float4 w1 = *(const float4*)(WqT + c * 64 + 32 + hc);
        q[0] = fmaf(w0.x, x, q[0]); q[1] = fmaf(w0.y, x, q[1]);
        q[2] = fmaf(w0.z, x, q[2]); q[3] = fmaf(w0.w, x, q[3]);
        q[4] = fmaf(w1.x, x, q[4]); q[5] = fmaf(w1.y, x, q[5]);
        q[6] = fmaf(w1.z, x, q[6]); q[7] = fmaf(w1.w, x, q[7]);
    }
    const float scl = 0.35355339059327373f;  // 1/sqrt(8)
    #pragma unroll
    for (int d = 0; d < 8; d++) q[d] *= scl;

    // ======== pass 2: energy[k] += (WkT[c].q) * nb[c][k], streaming r_c ========
    float e0[16];
    #pragma unroll
    for (int k = 0; k < 16; k++) e0[k] = 0.f;
    #pragma unroll 2
    for (int c = 0; c < CP3; c++) {
        float4 w0 = *(const float4*)(WkT + c * 64 + hc);
        float4 w1 = *(const float4*)(WkT + c * 64 + 32 + hc);
        // two partial chains for ILP
        float ra = fmaf(w0.x, q[0], w0.y * q[1]);
        float rb = fmaf(w0.z, q[2], w0.w * q[3]);
        ra = fmaf(w1.x, q[4], ra); rb = fmaf(w1.y, q[5], rb);
        ra = fmaf(w1.z, q[6], ra); rb = fmaf(w1.w, q[7], rb);
        float rc = ra + rb;
        float4 n0v = *(const float4*)(nbp + c * K_);
        float4 n1v = *(const float4*)(nbp + c * K_ + 4);
        float4 n2v = *(const float4*)(nbp + c * K_ + 8);
        float4 n3v = *(const float4*)(nbp + c * K_ + 12);
        e0[0]  = fmaf(rc, n0v.x, e0[0]);  e0[1]  = fmaf(rc, n0v.y, e0[1]);
        e0[2]  = fmaf(rc, n0v.z, e0[2]);  e0[3]  = fmaf(rc, n0v.w, e0[3]);
        e0[4]  = fmaf(rc, n1v.x, e0[4]);  e0[5]  = fmaf(rc, n1v.y, e0[5]);
        e0[6]  = fmaf(rc, n1v.z, e0[6]);  e0[7]  = fmaf(rc, n1v.w, e0[7]);
        e0[8]  = fmaf(rc, n2v.x, e0[8]);  e0[9]  = fmaf(rc, n2v.y, e0[9]);
        e0[10] = fmaf(rc, n2v.z, e0[10]); e0[11] = fmaf(rc, n2v.w, e0[11]);
        e0[12] = fmaf(rc, n3v.x, e0[12]); e0[13] = fmaf(rc, n3v.y, e0[13]);
        e0[14] = fmaf(rc, n3v.z, e0[14]); e0[15] = fmaf(rc, n3v.w, e0[15]);
    }

    // ======== softmax over 16 neighbors (thread-local) ========
    float m = e0[0];
    #pragma unroll
    for (int k = 1; k < 16; k++) m = fmaxf(m, e0[k]);
    float ssum = 0.f;
    #pragma unroll
    for (int k = 0; k < 16; k++) { e0[k] = __expf(e0[k] - m); ssum += e0[k]; }
    float inv = 1.f / ssum;
    #pragma unroll
    for (int k = 0; k < 16; k++) e0[k] *= inv;

    // ======== pass 3: o[d] += WvT[c][d] * (attn . nb[c][:]), streaming s_c ========
    float o[8];
    #pragma unroll
    for (int d = 0; d < 8; d++) o[d] = 0.f;
    #pragma unroll 2
    for (int c = 0; c < CP3; c++) {
        float4 n0v = *(const float4*)(nbp + c * K_);
        float4 n1v = *(const float4*)(nbp + c * K_ + 4);
        float4 n2v = *(const float4*)(nbp + c * K_ + 8);
        float4 n3v = *(const float4*)(nbp + c * K_ + 12);
        float s0 = e0[0] * n0v.x;
        float s1 = e0[4] * n1v.x;
        float s2 = e0[8] * n2v.x;
        float s3 = e0[12] * n3v.x;
        s0 = fmaf(e0[1],  n0v.y, s0); s1 = fmaf(e0[5],  n1v.y, s1);
        s2 = fmaf(e0[9],  n2v.y, s2); s3 = fmaf(e0[13], n3v.y, s3);
        s0 = fmaf(e0[2],  n0v.z, s0); s1 = fmaf(e0[6],  n1v.z, s1);
        s2 = fmaf(e0[10], n2v.z, s2); s3 = fmaf(e0[14], n3v.z, s3);
        s0 = fmaf(e0[3],  n0v.w, s0); s1 = fmaf(e0[7],  n1v.w, s1);
        s2 = fmaf(e0[11], n2v.w, s2); s3 = fmaf(e0[15], n3v.w, s3);
        float sc = (s0 + s1) + (s2 + s3);
        float4 w0 = *(const float4*)(WvT + c * 64 + hc);
        float4 w1 = *(const float4*)(WvT + c * 64 + 32 + hc);
        o[0] = fmaf(w0.x, sc, o[0]); o[1] = fmaf(w0.y, sc, o[1]);
        o[2] = fmaf(w0.z, sc, o[2]); o[3] = fmaf(w0.w, sc, o[3]);
        o[4] = fmaf(w1.x, sc, o[4]); o[5] = fmaf(w1.y, sc, o[5]);
        o[6] = fmaf(w1.z, sc, o[6]); o[7] = fmaf(w1.w, sc, o[7]);
    }

    // out[b, h*8+d, n0+p]
    const int n = n0 + p;
    #pragma unroll
    for (int d = 0; d < 8; d++)
        out[(b * C_ + h * 8 + d) * N_ + n] = o[d];
}

extern "C" void kernel_launch(void* const* d_in, const int* in_sizes, int n_in,
                              void* d_out, int out_size)
{
    (void)in_sizes; (void)n_in; (void)out_size;
    const float* pcd       = (const float*)d_in[0];
    const float* neighbors = (const float*)d_in[1];
    const float* xyz       = (const float*)d_in[2];
    const float* Wq        = (const float*)d_in[3];
    const float* Wk        = (const float*)d_in[4];
    const float* Wv        = (const float*)d_in[5];
    const int*   idx_all   = (const int*)d_in[6];
    float* out = (float*)d_out;

    cudaFuncSetAttribute(pt_attn_kernel,
                         cudaFuncAttributeMaxDynamicSharedMemorySize, SMEM_BYTES);

    const int total_points = B_ * N_;
    const int grid = total_points / PTS;   // 2048
    pt_attn_kernel<<<grid, THREADS, SMEM_BYTES>>>(
        pcd, neighbors, xyz, Wq, Wk, Wv, idx_all, out);
}

// round 8
// speedup vs baseline: 2.7435x; 1.5873x over previous
#include <cuda_runtime.h>
#include <math.h>

// Pe_i_CrossAttention: fused point-transformer local attention.
// B=4, C=64, N=16384, K=16, H=8, D=8.
// Algebraic fusion (never materialize k/v):
//   energy[h,k] = (Wk_h^T q_h) . nb_k   with r_c streamed
//   out[h]      = Wv_h @ (sum_k attn[h,k] nb_k) with s_c streamed
// R5 change: nb read directly from GLOBAL (pass3 re-read hits L2) -> smem
// 198KB -> 66KB -> 3 CTAs/SM (24 warps). W pre-permuted in global scratch.

#define B_      4
#define C_      64
#define N_      16384
#define K_      16
#define H_      8
#define CP3     67
#define PTS     32
#define THREADS 256
#define PC_STRIDE 68
#define W_ELEMS (CP3 * C_)          // 4288
#define CSTR    ((size_t)N_ * K_)   // float stride between c-rows of neighbors

// smem floats: 3*4288 (W) + 32*68 (pc) + 32*48 (sxyz) = 16576 -> 66304 bytes
#define SMEM_BYTES ((3 * W_ELEMS + PTS * PC_STRIDE + PTS * 48) * 4)

__device__ __align__(16) float g_WT[3 * W_ELEMS];

// Permute weights once: WT[c*64 + d4*32 + h*4 + dd] = W[(h*8+d4*4+dd)*67 + c]
// (8 heads' float4 reads cover 128 contiguous bytes -> conflict-free smem).
// 1/sqrt(D) folded into Wq.
__global__ void permute_w_kernel(const float* __restrict__ Wq,
                                 const float* __restrict__ Wk,
                                 const float* __restrict__ Wv)
{
    int e = blockIdx.x * blockDim.x + threadIdx.x;
    if (e >= W_ELEMS) return;
    int c  = e >> 6;
    int j  = e & 63;
    int d4 = j >> 5, h = (j >> 2) & 7, dd = j & 3;
    int o  = h * 8 + d4 * 4 + dd;
    g_WT[e]               = Wq[o * CP3 + c] * 0.35355339059327373f;
    g_WT[W_ELEMS + e]     = Wk[o * CP3 + c];
    g_WT[2 * W_ELEMS + e] = Wv[o * CP3 + c];
}

#define ACC16(rc, n0v, n1v, n2v, n3v)                                         \
    e0[0]  = fmaf(rc, n0v.x, e0[0]);  e0[1]  = fmaf(rc, n0v.y, e0[1]);        \
    e0[2]  = fmaf(rc, n0v.z, e0[2]);  e0[3]  = fmaf(rc, n0v.w, e0[3]);        \
    e0[4]  = fmaf(rc, n1v.x, e0[4]);  e0[5]  = fmaf(rc, n1v.y, e0[5]);        \
    e0[6]  = fmaf(rc, n1v.z, e0[6]);  e0[7]  = fmaf(rc, n1v.w, e0[7]);        \
    e0[8]  = fmaf(rc, n2v.x, e0[8]);  e0[9]  = fmaf(rc, n2v.y, e0[9]);        \
    e0[10] = fmaf(rc, n2v.z, e0[10]); e0[11] = fmaf(rc, n2v.w, e0[11]);       \
    e0[12] = fmaf(rc, n3v.x, e0[12]); e0[13] = fmaf(rc, n3v.y, e0[13]);       \
    e0[14] = fmaf(rc, n3v.z, e0[14]); e0[15] = fmaf(rc, n3v.w, e0[15]);

#define DOT16(n0v, n1v, n2v, n3v, sc)                                         \
    {                                                                          \
        float s0 = e0[0] * n0v.x,  s1 = e0[4] * n1v.x;                         \
        float s2 = e0[8] * n2v.x,  s3 = e0[12] * n3v.x;                        \
        s0 = fmaf(e0[1],  n0v.y, s0); s1 = fmaf(e0[5],  n1v.y, s1);            \
        s2 = fmaf(e0[9],  n2v.y, s2); s3 = fmaf(e0[13], n3v.y, s3);            \
        s0 = fmaf(e0[2],  n0v.z, s0); s1 = fmaf(e0[6],  n1v.z, s1);            \
        s2 = fmaf(e0[10], n2v.z, s2); s3 = fmaf(e0[14], n3v.z, s3);            \
        s0 = fmaf(e0[3],  n0v.w, s0); s1 = fmaf(e0[7],  n1v.w, s1);            \
        s2 = fmaf(e0[11], n2v.w, s2); s3 = fmaf(e0[15], n3v.w, s3);            \
        sc = (s0 + s1) + (s2 + s3);                                            \
    }

__global__ __launch_bounds__(THREADS, 3)
void pt_attn_kernel(const float* __restrict__ pcd,
                    const float* __restrict__ neighbors,
                    const float* __restrict__ xyz,
                    const int*   __restrict__ idx_all,
                    float*       __restrict__ out)
{
    extern __shared__ float sm[];
    float* WqT  = sm;                        // [67][64] permuted (pre-scaled)
    float* WkT  = WqT + W_ELEMS;
    float* WvT  = WkT + W_ELEMS;
    float* pc   = WvT + W_ELEMS;             // [32][68] center features
    float* sxyz = pc + PTS * PC_STRIDE;      // [32][3][16] gathered rel-xyz

    const int tid = threadIdx.x;
    const int g0  = blockIdx.x * PTS;        // 32 | 16384 -> never crosses batch
    const int b   = g0 / N_;
    const int n0  = g0 % N_;

    // ---- W: coalesced float4 copy from pre-permuted global scratch
    {
        const float4* src = (const float4*)g_WT;
        float4*       dst = (float4*)sm;
        #pragma unroll
        for (int e = tid; e < 3 * W_ELEMS / 4; e += THREADS) dst[e] = src[e];
    }
    // ---- center features (coalesced over p)
    for (int e = tid; e < C_ * PTS; e += THREADS) {
        int c = e >> 5, p = e & 31;
        pc[p * PC_STRIDE + c] = pcd[(b * C_ + c) * N_ + n0 + p];
    }
    for (int e = tid; e < 3 * PTS; e += THREADS) {
        int j = e >> 5, p = e & 31;
        pc[p * PC_STRIDE + 64 + j] = xyz[(b * 3 + j) * N_ + n0 + p];
    }
    // ---- gathered xyz rows (xyz is 768 KB -> L2-resident)
    for (int e = tid; e < PTS * K_; e += THREADS) {
        int p = e >> 4, k = e & 15;
        int idx = idx_all[(b * N_ + n0 + p) * K_ + k];
        #pragma unroll
        for (int j = 0; j < 3; j++)
            sxyz[p * 48 + j * 16 + k] = xyz[(b * 3 + j) * N_ + idx];
    }
    __syncthreads();

    // ---- per-thread: one (point, head)
    const int lane = tid & 31;
    const int w    = tid >> 5;
    const int psub = lane & 3;
    const int h    = lane >> 2;
    const int p    = w * 4 + psub;
    const int n    = n0 + p;
    const float* pcp = pc + p * PC_STRIDE;
    const float* sxp = sxyz + p * 48;
    const float* nbg = neighbors + ((size_t)(b * C_) * N_ + (size_t)n) * K_;
    const int hc = h * 4;

    // ======== pass 1: q_h = Wq_h @ pcd_cat (scale pre-folded) ========
    float q[8];
    #pragma unroll
    for (int d = 0; d < 8; d++) q[d] = 0.f;
    #pragma unroll 2
    for (int c = 0; c < CP3; c++) {
        float x = pcp[c];
        float4 w0 = *(const float4*)(WqT + c * 64 + hc);
        float4 w1 = *(const float4*)(WqT + c * 64 + 32 + hc);
        q[0] = fmaf(w0.x, x, q[0]); q[1] = fmaf(w0.y, x, q[1]);
        q[2] = fmaf(w0.z, x, q[2]); q[3] = fmaf(w0.w, x, q[3]);
        q[4] = fmaf(w1.x, x, q[4]); q[5] = fmaf(w1.y, x, q[5]);
        q[6] = fmaf(w1.z, x, q[6]); q[7] = fmaf(w1.w, x, q[7]);
    }

    // ======== pass 2: energy[k] += (WkT[c].q) * nb[c][k] ========
    float e0[16];
    #pragma unroll
    for (int k = 0; k < 16; k++) e0[k] = 0.f;
    #pragma unroll 4
    for (int c = 0; c < C_; c++) {
        const float4* nrow = (const float4*)(nbg + (size_t)c * CSTR);
        float4 n0v = nrow[0], n1v = nrow[1], n2v = nrow[2], n3v = nrow[3];
        float4 w0 = *(const float4*)(WkT + c * 64 + hc);
        float4 w1 = *(const float4*)(WkT + c * 64 + 32 + hc);
        float ra = fmaf(w0.x, q[0], w0.y * q[1]);
        float rb = fmaf(w0.z, q[2], w0.w * q[3]);
        ra = fmaf(w1.x, q[4], ra); rb = fmaf(w1.y, q[5], rb);
        ra = fmaf(w1.z, q[6], ra); rb = fmaf(w1.w, q[7], rb);
        float rc = ra + rb;
        ACC16(rc, n0v, n1v, n2v, n3v)
    }
    #pragma unroll
    for (int j = 0; j < 3; j++) {            // xyz tail rows from smem
        int c = C_ + j;
        const float4* nrow = (const float4*)(sxp + j * 16);
        float4 n0v = nrow[0], n1v = nrow[1], n2v = nrow[2], n3v = nrow[3];
        float4 w0 = *(const float4*)(WkT + c * 64 + hc);
        float4 w1 = *(const float4*)(WkT + c * 64 + 32 + hc);
        float ra = fmaf(w0.x, q[0], w0.y * q[1]);
        float rb = fmaf(w0.z, q[2], w0.w * q[3]);
        ra = fmaf(w1.x, q[4], ra); rb = fmaf(w1.y, q[5], rb);
        ra = fmaf(w1.z, q[6], ra); rb = fmaf(w1.w, q[7], rb);
        float rc = ra + rb;
        ACC16(rc, n0v, n1v, n2v, n3v)
    }

    // ======== softmax over 16 neighbors (thread-local) ========
    float m = e0[0];
    #pragma unroll
    for (int k = 1; k < 16; k++) m = fmaxf(m, e0[k]);
    float ssum = 0.f;
    #pragma unroll
    for (int k = 0; k < 16; k++) { e0[k] = __expf(e0[k] - m); ssum += e0[k]; }
    float inv = 1.f / ssum;
    #pragma unroll
    for (int k = 0; k < 16; k++) e0[k] *= inv;

    // ======== pass 3: o[d] += WvT[c][d] * (attn . nb[c][:]) ========
    float o[8];
    #pragma unroll
    for (int d = 0; d < 8; d++) o[d] = 0.f;
    #pragma unroll 4
    for (int c = 0; c < C_; c++) {
        const float4* nrow = (const float4*)(nbg + (size_t)c * CSTR);
        float4 n0v = nrow[0], n1v = nrow[1], n2v = nrow[2], n3v = nrow[3];
        float sc;
        DOT16(n0v, n1v, n2v, n3v, sc)
        float4 w0 = *(const float4*)(WvT + c * 64 + hc);
        float4 w1 = *(const float4*)(WvT + c * 64 + 32 + hc);
        o[0] = fmaf(w0.x, sc, o[0]); o[1] = fmaf(w0.y, sc, o[1]);
        o[2] = fmaf(w0.z, sc, o[2]); o[3] = fmaf(w0.w, sc, o[3]);
        o[4] = fmaf(w1.x, sc, o[4]); o[5] = fmaf(w1.y, sc, o[5]);
        o[6] = fmaf(w1.z, sc, o[6]); o[7] = fmaf(w1.w, sc, o[7]);
    }
    #pragma unroll
    for (int j = 0; j < 3; j++) {
        int c = C_ + j;
        const float4* nrow = (const float4*)(sxp + j * 16);
        float4 n0v = nrow[0], n1v = nrow[1], n2v = nrow[2], n3v = nrow[3];
        float sc;
        DOT16(n0v, n1v, n2v, n3v, sc)
        float4 w0 = *(const float4*)(WvT + c * 64 + hc);
        float4 w1 = *(const float4*)(WvT + c * 64 + 32 + hc);
        o[0] = fmaf(w0.x, sc, o[0]); o[1] = fmaf(w0.y, sc, o[1]);
        o[2] = fmaf(w0.z, sc, o[2]); o[3] = fmaf(w0.w, sc, o[3]);
        o[4] = fmaf(w1.x, sc, o[4]); o[5] = fmaf(w1.y, sc, o[5]);
        o[6] = fmaf(w1.z, sc, o[6]); o[7] = fmaf(w1.w, sc, o[7]);
    }

    // out[b, h*8+d, n]
    #pragma unroll
    for (int d = 0; d < 8; d++)
        out[(b * C_ + h * 8 + d) * N_ + n] = o[d];
}

extern "C" void kernel_launch(void* const* d_in, const int* in_sizes, int n_in,
                              void* d_out, int out_size)
{
    (void)in_sizes; (void)n_in; (void)out_size;
    const float* pcd       = (const float*)d_in[0];
    const float* neighbors = (const float*)d_in[1];
    const float* xyz       = (const float*)d_in[2];
    const float* Wq        = (const float*)d_in[3];
    const float* Wk        = (const float*)d_in[4];
    const float* Wv        = (const float*)d_in[5];
    const int*   idx_all   = (const int*)d_in[6];
    float* out = (float*)d_out;

    permute_w_kernel<<<(W_ELEMS + 255) / 256, 256>>>(Wq, Wk, Wv);

    cudaFuncSetAttribute(pt_attn_kernel,
                         cudaFuncAttributeMaxDynamicSharedMemorySize, SMEM_BYTES);

    const int grid = (B_ * N_) / PTS;   // 2048
    pt_attn_kernel<<<grid, THREADS, SMEM_BYTES>>>(
        pcd, neighbors, xyz, idx_all, out);
}

// round 10
// speedup vs baseline: 3.4770x; 1.2673x over previous
#include <cuda_runtime.h>
#include <math.h>

// Pe_i_CrossAttention: fused point-transformer local attention.
// B=4, C=64, N=16384, K=16, H=8, D=8.
// R8/R9: warp = 2 points, lane = (p, kh, h).
//   - nb LDG: warp touches exactly one 128B line per instr (no head dup)
//   - r/s dots computed as per-lane halves + one shfl_xor(2) -> no FMA dup
// energy[h,k] = (Wk_h^T q_h).nb_k ; out[h] = Wv_h @ (sum_k attn_k nb_k)

#define B_      4
#define C_      64
#define N_      16384
#define K_      16
#define CP3     67
#define PTS     16                  // points per CTA (8 warps x 2)
#define THREADS 256
#define PC_STRIDE 68
#define SX_STRIDE 48
#define W_ELEMS (CP3 * C_)          // 4288
#define CSTR    ((size_t)N_ * K_)   // float stride between c-rows of neighbors

// smem floats: 3*4288 (W) + 16*68 (pc) + 16*48 (sxyz) = 14720 -> 58880 B
#define SMEM_BYTES ((3 * W_ELEMS + PTS * PC_STRIDE + PTS * SX_STRIDE) * 4)

__device__ __align__(16) float g_WT[3 * W_ELEMS];

// Permute weights once: WT[c*64 + o] = W[o*67 + c], o = h*8 + d.
// 1/sqrt(D) folded into Wq.
__global__ void permute_w_kernel(const float* __restrict__ Wq,
                                 const float* __restrict__ Wk,
                                 const float* __restrict__ Wv)
{
    int e = blockIdx.x * blockDim.x + threadIdx.x;
    if (e >= W_ELEMS) return;
    int c = e >> 6;
    int o = e & 63;
    g_WT[e]               = Wq[o * CP3 + c] * 0.35355339059327373f;
    g_WT[W_ELEMS + e]     = Wk[o * CP3 + c];
    g_WT[2 * W_ELEMS + e] = Wv[o * CP3 + c];
}

__global__ __launch_bounds__(THREADS, 3)
void pt_attn_kernel(const float* __restrict__ pcd,
                    const float* __restrict__ neighbors,
                    const float* __restrict__ xyz,
                    const int*   __restrict__ idx_all,
                    float*       __restrict__ out)
{
    extern __shared__ float sm[];
    float* WqT  = sm;                        // [67][64]
    float* WkT  = WqT + W_ELEMS;
    float* WvT  = WkT + W_ELEMS;
    float* pc   = WvT + W_ELEMS;             // [16][68] center features
    float* sxyz = pc + PTS * PC_STRIDE;      // [16][3][16] gathered rel-xyz

    const int tid = threadIdx.x;
    const int g0  = blockIdx.x * PTS;        // 16 | 16384 -> never crosses batch
    const int b   = g0 / N_;
    const int n0  = g0 % N_;

    // ---- W: coalesced float4 copy from pre-permuted global scratch
    {
        const float4* src = (const float4*)g_WT;
        float4*       dst = (float4*)sm;
        for (int e = tid; e < 3 * W_ELEMS / 4; e += THREADS) dst[e] = src[e];
    }
    // ---- center features: pc[p][c], coalesced over p (16-wide)
    for (int e = tid; e < C_ * PTS; e += THREADS) {
        int c = e >> 4, p = e & 15;
        pc[p * PC_STRIDE + c] = pcd[(b * C_ + c) * N_ + n0 + p];
    }
    for (int e = tid; e < 3 * PTS; e += THREADS) {
        int j = e >> 4, p = e & 15;
        pc[p * PC_STRIDE + 64 + j] = xyz[(b * 3 + j) * N_ + n0 + p];
    }
    // ---- gathered xyz rows (xyz is 768 KB -> L2-resident)
    for (int e = tid; e < PTS * K_; e += THREADS) {
        int p = e >> 4, k = e & 15;
        int idx = idx_all[(b * N_ + n0 + p) * K_ + k];
        #pragma unroll
        for (int j = 0; j < 3; j++)
            sxyz[p * SX_STRIDE + j * 16 + k] = xyz[(b * 3 + j) * N_ + idx];
    }
    __syncthreads();

    // ---- lane mapping: warp = 2 points
    const int lane = tid & 31;
    const int w    = tid >> 5;
    const int psub = lane & 1;
    const int kh   = (lane >> 1) & 1;        // which 8-k half
    const int h    = lane >> 2;              // head
    const int pidx = w * 2 + psub;
    const int n    = n0 + pidx;
    const int wo   = h * 8 + kh * 4;         // W column offset for this lane
    const float* pcp = pc + pidx * PC_STRIDE;
    const float* sxp = sxyz + pidx * SX_STRIDE + kh * 8;
    const float* nbg = neighbors + ((size_t)(b * C_) * N_ + (size_t)n) * K_ + kh * 8;

    // ======== pass 1: q half — q[h, kh*4 + 0..3] (scale pre-folded) ========
    float q0 = 0.f, q1 = 0.f, q2 = 0.f, q3 = 0.f;
    #pragma unroll 4
    for (int c = 0; c < CP3; c++) {
        float x = pcp[c];
        float4 wq = *(const float4*)(WqT + c * 64 + wo);
        q0 = fmaf(wq.x, x, q0); q1 = fmaf(wq.y, x, q1);
        q2 = fmaf(wq.z, x, q2); q3 = fmaf(wq.w, x, q3);
    }

    // ======== pass 2: energy over own 8 k ========
    float e0[8];
    #pragma unroll
    for (int k = 0; k < 8; k++) e0[k] = 0.f;
    #pragma unroll 4
    for (int c = 0; c < C_; c++) {
        const float4* nr = (const float4*)(nbg + (size_t)c * CSTR);
        float4 na = nr[0], nb4 = nr[1];
        float4 wk = *(const float4*)(WkT + c * 64 + wo);
        float rp = fmaf(wk.x, q0, wk.y * q1);
        rp = fmaf(wk.z, q2, rp);
        rp = fmaf(wk.w, q3, rp);
        float r = rp + __shfl_xor_sync(0xffffffffu, rp, 2);
        e0[0] = fmaf(r, na.x, e0[0]);  e0[1] = fmaf(r, na.y, e0[1]);
        e0[2] = fmaf(r, na.z, e0[2]);  e0[3] = fmaf(r, na.w, e0[3]);
        e0[4] = fmaf(r, nb4.x, e0[4]); e0[5] = fmaf(r, nb4.y, e0[5]);
        e0[6] = fmaf(r, nb4.z, e0[6]); e0[7] = fmaf(r, nb4.w, e0[7]);
    }
    #pragma unroll
    for (int j = 0; j < 3; j++) {            // xyz tail rows from smem
        int c = C_ + j;
        const float4* nr = (const float4*)(sxp + j * 16);
        float4 na = nr[0], nb4 = nr[1];
        float4 wk = *(const float4*)(WkT + c * 64 + wo);
        float rp = fmaf(wk.x, q0, wk.y * q1);
        rp = fmaf(wk.z, q2, rp);
        rp = fmaf(wk.w, q3, rp);
        float r = rp + __shfl_xor_sync(0xffffffffu, rp, 2);
        e0[0] = fmaf(r, na.x, e0[0]);  e0[1] = fmaf(r, na.y, e0[1]);
        e0[2] = fmaf(r, na.z, e0[2]);  e0[3] = fmaf(r, na.w, e0[3]);
        e0[4] = fmaf(r, nb4.x, e0[4]); e0[5] = fmaf(r, nb4.y, e0[5]);
        e0[6] = fmaf(r, nb4.z, e0[6]); e0[7] = fmaf(r, nb4.w, e0[7]);
    }

    // ======== softmax over 16 k (8 local + partner half) ========
    float m = e0[0];
    #pragma unroll
    for (int k = 1; k < 8; k++) m = fmaxf(m, e0[k]);
    m = fmaxf(m, __shfl_xor_sync(0xffffffffu, m, 2));
    float ssum = 0.f;
    #pragma unroll
    for (int k = 0; k < 8; k++) { e0[k] = __expf(e0[k] - m); ssum += e0[k]; }
    ssum += __shfl_xor_sync(0xffffffffu, ssum, 2);
    float inv = 1.f / ssum;
    #pragma unroll
    for (int k = 0; k < 8; k++) e0[k] *= inv;

    // ======== pass 3: o[d] += Wv[c, wo+d] * s_c, s via partner shuffle ========
    float o0 = 0.f, o1 = 0.f, o2 = 0.f, o3 = 0.f;
    #pragma unroll 4
    for (int c = 0; c < C_; c++) {
        const float4* nr = (const float4*)(nbg + (size_t)c * CSTR);
        float4 na = nr[0], nb4 = nr[1];
        float sa = fmaf(e0[0], na.x, e0[1] * na.y);
        float sb = fmaf(e0[2], na.z, e0[3] * na.w);
        sa = fmaf(e0[4], nb4.x, sa); sb = fmaf(e0[5], nb4.y, sb);
        sa = fmaf(e0[6], nb4.z, sa); sb = fmaf(e0[7], nb4.w, sb);
        float sp = sa + sb;
        float s = sp + __shfl_xor_sync(0xffffffffu, sp, 2);
        float4 wv = *(const float4*)(WvT + c * 64 + wo);
        o0 = fmaf(wv.x, s, o0); o1 = fmaf(wv.y, s, o1);
        o2 = fmaf(wv.z, s, o2); o3 = fmaf(wv.w, s, o3);
    }
    #pragma unroll
    for (int j = 0; j < 3; j++) {
        int c = C_ + j;
        const float4* nr = (const float4*)(sxp + j * 16);
        float4 na = nr[0], nb4 = nr[1];
        float sa = fmaf(e0[0], na.x, e0[1] * na.y);
        float sb = fmaf(e0[2], na.z, e0[3] * na.w);
        sa = fmaf(e0[4], nb4.x, sa); sb = fmaf(e0[5], nb4.y, sb);
        sa = fmaf(e0[6], nb4.z, sa); sb = fmaf(e0[7], nb4.w, sb);
        float sp = sa + sb;
        float s = sp + __shfl_xor_sync(0xffffffffu, sp, 2);
        float4 wv = *(const float4*)(WvT + c * 64 + wo);
        o0 = fmaf(wv.x, s, o0); o1 = fmaf(wv.y, s, o1);
        o2 = fmaf(wv.z, s, o2); o3 = fmaf(wv.w, s, o3);
    }

    // ---- store: out[b, wo + d, n] (scattered 4B; tiny vs main loop)
    float* ob = out + ((size_t)(b * C_ + wo)) * N_ + n;
    ob[0]      = o0;
    ob[N_]     = o1;
    ob[2 * N_] = o2;
    ob[3 * N_] = o3;
}

extern "C" void kernel_launch(void* const* d_in, const int* in_sizes, int n_in,
                              void* d_out, int out_size)
{
    (void)in_sizes; (void)n_in; (void)out_size;
    const float* pcd       = (const float*)d_in[0];
    const float* neighbors = (const float*)d_in[1];
    const float* xyz       = (const float*)d_in[2];
    const float* Wq        = (const float*)d_in[3];
    const float* Wk        = (const float*)d_in[4];
    const float* Wv        = (const float*)d_in[5];
    const int*   idx_all   = (const int*)d_in[6];
    float* out = (float*)d_out;

    permute_w_kernel<<<(W_ELEMS + 255) / 256, 256>>>(Wq, Wk, Wv);

    cudaFuncSetAttribute(pt_attn_kernel,
                         cudaFuncAttributeMaxDynamicSharedMemorySize, SMEM_BYTES);

    const int grid = (B_ * N_) / PTS;   // 4096
    pt_attn_kernel<<<grid, THREADS, SMEM_BYTES>>>(
        pcd, neighbors, xyz, idx_all, out);
}